// round 7
// baseline (speedup 1.0000x reference)
#include <cuda_runtime.h>
#include <cuda_fp16.h>
#include <cstdint>
#include <math.h>

#define S_    64
#define I_    128
#define NO_   64
#define K_    64
#define D_    64
#define B_    64
#define TLEN_ 256
#define THR_  0.01f
#define NTHREADS 1024

#define WELEM  ((size_t)S_ * I_ * D_ * S_)
#define TOTAL4 (WELEM / 4)

__device__ __half g_Th[WELEM];
__device__ __half g_Oh[WELEM];
__device__ float  g_pvt[I_ * S_ * D_];   // pv transposed: [i][s][d]
__device__ float  g_pgt[I_ * S_];        // push_gate transposed: [i][s]
__device__ float  g_ppt[I_ * S_];        // pop_gate transposed: [i][s]

__global__ __launch_bounds__(256)
void cvt_kernel(const float* __restrict__ Ts, const float* __restrict__ Os) {
    size_t i = (size_t)blockIdx.x * blockDim.x + threadIdx.x;
    if (i >= TOTAL4) return;
    float4 a = ((const float4*)Ts)[i];
    float4 b = ((const float4*)Os)[i];
    __half2 a0 = __floats2half2_rn(a.x, a.y);
    __half2 a1 = __floats2half2_rn(a.z, a.w);
    __half2 b0 = __floats2half2_rn(b.x, b.y);
    __half2 b1 = __floats2half2_rn(b.z, b.w);
    uint2 ua, ub;
    ua.x = *(unsigned*)&a0; ua.y = *(unsigned*)&a1;
    ub.x = *(unsigned*)&b0; ub.y = *(unsigned*)&b1;
    ((uint2*)g_Th)[i] = ua;
    ((uint2*)g_Oh)[i] = ub;
}

__global__ __launch_bounds__(256)
void tr_kernel(const float* __restrict__ pg, const float* __restrict__ pp,
               const float* __restrict__ pv) {
    int idx = blockIdx.x * blockDim.x + threadIdx.x;
    if (idx < I_ * S_ * D_) {
        int d = idx & 63;
        int s = (idx >> 6) & 63;
        int i = idx >> 12;
        g_pvt[idx] = pv[(s * I_ + i) * D_ + d];
    }
    if (idx < I_ * S_) {
        int s = idx & 63;
        int i = idx >> 6;
        g_pgt[idx] = pg[s * I_ + i];
        g_ppt[idx] = pp[s * I_ + i];
    }
}

// ---------- helpers ----------
__device__ __forceinline__ unsigned int s2u(const void* p) {
    unsigned int a;
    asm("{ .reg .u64 t; cvta.to.shared.u64 t, %1; cvt.u32.u64 %0, t; }" : "=r"(a) : "l"(p));
    return a;
}
__device__ __forceinline__ unsigned int ctarank() {
    unsigned int r; asm("mov.u32 %0, %%cluster_ctarank;" : "=r"(r)); return r;
}
__device__ __forceinline__ void arrive_peer(unsigned int local_bar, unsigned int peer) {
    asm volatile(
        "{ .reg .b32 ra;\n\t"
        "mapa.shared::cluster.u32 ra, %0, %1;\n\t"
        "mbarrier.arrive.release.cluster.shared::cluster.b64 _, [ra]; }"
        :: "r"(local_bar), "r"(peer) : "memory");
}
__device__ __forceinline__ void wait_bar_cluster(unsigned int bar, unsigned int parity) {
    asm volatile(
        "{\n\t.reg .pred P;\n\t"
        "WL%=:\n\t"
        "mbarrier.try_wait.parity.acquire.cluster.shared::cta.b64 P, [%0], %1, 0x989680;\n\t"
        "@P bra.uni WD%=;\n\t"
        "bra.uni WL%=;\n\t"
        "WD%=:\n\t}"
        :: "r"(bar), "r"(parity) : "memory");
}
__device__ __forceinline__ float ld_peer_f32(unsigned int local_addr, unsigned int peer) {
    unsigned int ra, v;
    asm("mapa.shared::cluster.u32 %0, %1, %2;" : "=r"(ra) : "r"(local_addr), "r"(peer));
    asm volatile("ld.shared::cluster.b32 %0, [%1];" : "=r"(v) : "r"(ra) : "memory");
    return __uint_as_float(v);
}
__device__ __forceinline__ float tanh_fast(float x) {
    float y; asm("tanh.approx.f32 %0, %1;" : "=f"(y) : "f"(x)); return y;
}
__device__ __forceinline__ void pf_l2(const void* p) {
    asm volatile("prefetch.global.L2 [%0];" :: "l"(p));
}

// in-place softmax over 64 values: 8 per lane across an 8-lane group
__device__ __forceinline__ void softmax8(float* a) {
    float m = a[0];
    #pragma unroll
    for (int j = 1; j < 8; j++) m = fmaxf(m, a[j]);
    #pragma unroll
    for (int o = 4; o > 0; o >>= 1) m = fmaxf(m, __shfl_xor_sync(0xffffffffu, m, o, 8));
    float s = 0.f;
    #pragma unroll
    for (int j = 0; j < 8; j++) { a[j] = __expf(a[j] - m); s += a[j]; }
    #pragma unroll
    for (int o = 4; o > 0; o >>= 1) s += __shfl_xor_sync(0xffffffffu, s, o, 8);
    float inv = 1.0f / s;
    #pragma unroll
    for (int j = 0; j < 8; j++) a[j] *= inv;
}

__global__ __launch_bounds__(NTHREADS, 1) __cluster_dims__(2, 1, 1)
void fpt_kernel(const int*   __restrict__ seq,
                const float* __restrict__ initl,
                float*       __restrict__ out)
{
    __shared__ float   content[K_ * D_];
    __shared__ float   partO[32 * 64];
    __shared__ float   partT[32 * 64];
    __shared__ float   state[S_];
    __shared__ float   pb[2][K_];       // pointer double buffer
    __shared__ __half2 stTop2[D_];
    __shared__ float   pushv[D_];
    __shared__ float   scal[4];
    __shared__ float   exch[2][128];
    __shared__ int     seq_s[TLEN_ + 1];
    __shared__ __align__(8) unsigned long long bar[2];

    const int tid   = threadIdx.x;
    const int wid   = tid >> 5;
    const int lane  = tid & 31;
    const int lc    = lane & 7;     // col block (8 halves)
    const int lr    = lane >> 3;    // row-in-group-of-4
    const unsigned int rank = ctarank();
    const unsigned int peer = rank ^ 1u;
    const int b     = blockIdx.x >> 1;
    const int s     = (int)rank * 32 + wid;

    // ---- init
    if (tid < S_) pushv[tid] = initl[tid];
    for (int e = tid; e <= TLEN_; e += NTHREADS)
        seq_s[e] = (e < TLEN_) ? seq[b * TLEN_ + e] : 0;
    __syncthreads();
    if (tid == 0) {
        float m = -1e30f;
        for (int i = 0; i < S_; i++) m = fmaxf(m, pushv[i]);
        float ssum = 0.f;
        for (int i = 0; i < S_; i++) { float e = expf(pushv[i] - m); partO[i] = e; ssum += e; }
        scal[2] = ssum;
        asm volatile("mbarrier.init.shared.b64 [%0], 1;" :: "r"(s2u(&bar[0])) : "memory");
        asm volatile("mbarrier.init.shared.b64 [%0], 1;" :: "r"(s2u(&bar[1])) : "memory");
    }
    __syncthreads();
    if (tid < S_) state[tid] = partO[tid] / scal[2];
    for (int e = tid; e < K_ * D_; e += NTHREADS) content[e] = 0.f;
    if (tid < K_) {
        pb[0][tid] = (tid == 0) ? 1.f : 0.f;
        pb[1][tid] = 0.f;
    }
    if (tid < D_) stTop2[tid] = __float2half2_rn(0.f);
    __syncthreads();

    asm volatile("barrier.cluster.arrive.aligned;" ::: "memory");
    asm volatile("barrier.cluster.wait.aligned;" ::: "memory");

    const unsigned int bar_u[2] = { s2u(&bar[0]), s2u(&bar[1]) };
    const unsigned int exch_u   = s2u(&exch[0][0]);

    // ---- prologue tail for t=0: gates(0), pushv(0)  (stTop2(0)=0 already)
    {
        const int sym0 = seq_s[0];
        if (wid == 2) {
            float a = g_pgt[sym0 * 64 + lane] * state[lane]
                    + g_pgt[sym0 * 64 + 32 + lane] * state[lane + 32];
            #pragma unroll
            for (int o = 16; o > 0; o >>= 1) a += __shfl_xor_sync(0xffffffffu, a, o);
            if (lane == 0) scal[0] = 1.f / (1.f + __expf(-a));
        } else if (wid == 3) {
            float a = g_ppt[sym0 * 64 + lane] * state[lane]
                    + g_ppt[sym0 * 64 + 32 + lane] * state[lane + 32];
            #pragma unroll
            for (int o = 16; o > 0; o >>= 1) a += __shfl_xor_sync(0xffffffffu, a, o);
            if (lane == 0) scal[1] = 1.f / (1.f + __expf(-a));
        } else if (wid >= 4 && wid < 8) {
            const int d  = (wid - 4) * 16 + (lane & 15);
            const int sb = (lane >> 4) * 32;
            float acc = 0.f;
            #pragma unroll 8
            for (int j = 0; j < 32; j++)
                acc += state[sb + j] * g_pvt[sym0 * 4096 + (sb + j) * 64 + d];
            acc += __shfl_xor_sync(0xffffffffu, acc, 16);
            if ((lane >> 4) == 0) pushv[d] = tanh_fast(acc);
        }
    }

    for (int t = 0; t < TLEN_; t++) {
        const int sym  = seq_s[t];
        const int sym1 = seq_s[t + 1];
        const int p    = t & 1;
        const int np   = p ^ 1;
        const unsigned int par = (unsigned int)(t >> 1) & 1u;

        __syncthreads();   // B3/loop-top: stTop2, scal, pushv, state, pb[p] valid

        // ---- pointer update: all warps redundantly, in registers
        const float pushs = scal[0];
        const float pops  = scal[1];
        const int i0 = lane * 2;
        float q0, q1;
        {
            float p0 = pb[p][i0], p1 = pb[p][i0 + 1];
            float d1 = __shfl_down_sync(0xffffffffu, p0, 1);
            if (lane == 31) d1 = 0.f;
            if (pops > THR_) {
                p0 = pops * p1 + (1.f - pops) * p0;
                p1 = pops * d1 + (1.f - pops) * p1;
            }
            float u0 = __shfl_up_sync(0xffffffffu, p1, 1);
            if (lane == 0) u0 = 0.f;
            q0 = pushs * u0 + (1.f - pushs) * p0;
            q1 = pushs * p0 + (1.f - pushs) * p1;
            float n0 = (pushs > THR_) ? q0 : p0;
            float n1 = (pushs > THR_) ? q1 : p1;
            if (wid == 8) { pb[np][i0] = n0; pb[np][i0 + 1] = n1; }
        }

        // ---- content update (in the shadow of phase-2 loads)
        if (pushs > THR_) {
            const int k0   = tid >> 6;
            const float myq = (k0 & 1) ? q1 : q0;
            const float pd  = pushv[tid & 63];
            #pragma unroll
            for (int i = 0; i < 4; i++) {
                float wk = __shfl_sync(0xffffffffu, myq, (k0 >> 1) + 8 * i);
                int e = tid + 1024 * i;
                content[e] = content[e] * (1.f - wk) + pd * wk;
            }
        }

        // ---- L2 prefetch for step t+1
        {
            const char* pO = (const char*)(g_Oh + (size_t)(s * I_ + sym1) * 4096);
            const char* pT = (const char*)(g_Th + (size_t)(s * I_ + sym1) * 4096);
            pf_l2(pO + lane * 128); pf_l2(pO + 4096 + lane * 128);
            pf_l2(pT + lane * 128); pf_l2(pT + 4096 + lane * 128);
            if (wid >= 4 && wid < 8)
                pf_l2((const char*)(g_pvt + sym1 * 4096 + (wid - 4) * 1024) + lane * 128);
            if (wid == 2 && lane < 2) pf_l2((const char*)(g_pgt + sym1 * 64) + lane * 128);
            if (wid == 3 && lane < 2) pf_l2((const char*)(g_ppt + sym1 * 64) + lane * 128);
        }

        // ---- phase 2: warp = one s-row; LDG.128 + HFMA2, fp32 flush per 8 d
        {
            const uint4* O4 = (const uint4*)(g_Oh + (size_t)(s * I_ + sym) * 4096);
            const uint4* T4 = (const uint4*)(g_Th + (size_t)(s * I_ + sym) * 4096);
            float fO[8] = {0,0,0,0,0,0,0,0};
            float fT[8] = {0,0,0,0,0,0,0,0};
            const __half2 hz = __float2half2_rn(0.f);
            #pragma unroll
            for (int chunk = 0; chunk < 2; chunk++) {
                __half2 hO[4] = {hz, hz, hz, hz};
                __half2 hT[4] = {hz, hz, hz, hz};
                #pragma unroll
                for (int i = 0; i < 8; i++) {
                    const int ii = chunk * 8 + i;
                    const __half2 td2 = stTop2[ii * 4 + lr];
                    uint4 v = O4[ii * 32 + lane];
                    hO[0] = __hfma2(td2, *(__half2*)&v.x, hO[0]);
                    hO[1] = __hfma2(td2, *(__half2*)&v.y, hO[1]);
                    hO[2] = __hfma2(td2, *(__half2*)&v.z, hO[2]);
                    hO[3] = __hfma2(td2, *(__half2*)&v.w, hO[3]);
                    uint4 u = T4[ii * 32 + lane];
                    hT[0] = __hfma2(td2, *(__half2*)&u.x, hT[0]);
                    hT[1] = __hfma2(td2, *(__half2*)&u.y, hT[1]);
                    hT[2] = __hfma2(td2, *(__half2*)&u.z, hT[2]);
                    hT[3] = __hfma2(td2, *(__half2*)&u.w, hT[3]);
                }
                #pragma unroll
                for (int c = 0; c < 4; c++) {
                    float2 f = __half22float2(hO[c]);
                    fO[2 * c] += f.x; fO[2 * c + 1] += f.y;
                    f = __half22float2(hT[c]);
                    fT[2 * c] += f.x; fT[2 * c + 1] += f.y;
                }
            }
            #pragma unroll
            for (int j = 0; j < 8; j++) {
                fO[j] += __shfl_xor_sync(0xffffffffu, fO[j], 8);
                fO[j] += __shfl_xor_sync(0xffffffffu, fO[j], 16);
                fT[j] += __shfl_xor_sync(0xffffffffu, fT[j], 8);
                fT[j] += __shfl_xor_sync(0xffffffffu, fT[j], 16);
            }
            softmax8(fO);
            softmax8(fT);
            const float st = state[s];
            if (lr == 0) {
                float4 w;
                w.x = st * fO[0]; w.y = st * fO[1]; w.z = st * fO[2]; w.w = st * fO[3];
                *(float4*)&partO[wid * 64 + lc * 8]     = w;
                w.x = st * fO[4]; w.y = st * fO[5]; w.z = st * fO[6]; w.w = st * fO[7];
                *(float4*)&partO[wid * 64 + lc * 8 + 4] = w;
                w.x = st * fT[0]; w.y = st * fT[1]; w.z = st * fT[2]; w.w = st * fT[3];
                *(float4*)&partT[wid * 64 + lc * 8]     = w;
                w.x = st * fT[4]; w.y = st * fT[5]; w.z = st * fT[6]; w.w = st * fT[7];
                *(float4*)&partT[wid * 64 + lc * 8 + 4] = w;
            }
        }
        __syncthreads();   // B1: partials + content(t+1) + pb[np] ready

        // ---- B1..B2: warps 0-3 reduce+exchange;  warps 4-7 stack_top(t+1)
        if (tid < 128) {
            float mine = 0.f;
            if (tid < 64) {
                #pragma unroll
                for (int r = 0; r < 32; r++) mine += partO[r * 64 + tid];
            } else {
                const int c = tid - 64;
                #pragma unroll
                for (int r = 0; r < 32; r++) mine += partT[r * 64 + c];
            }
            exch[p][tid] = mine;
            asm volatile("bar.sync 1, 128;" ::: "memory");
            if (tid == 0) arrive_peer(bar_u[p], peer);
            wait_bar_cluster(bar_u[p], par);
            float pval_ = ld_peer_f32(exch_u + (unsigned int)(p * 128 + tid) * 4u, peer);
            if (tid < 64) {
                if (rank == 0)
                    out[((size_t)b * TLEN_ + t) * NO_ + tid] = mine + pval_;
            } else {
                state[tid - 64] = mine + pval_;   // state(t+1)
            }
        } else if (wid >= 4 && wid < 8) {
            // stack_top(t+1) from content(t+1), pb[np]
            const int d  = (wid - 4) * 16 + (lane & 15);
            const int kb = (lane >> 4) * 32;
            float acc = 0.f;
            #pragma unroll 8
            for (int j = 0; j < 32; j++)
                acc += pb[np][kb + j] * content[(kb + j) * D_ + d];
            acc += __shfl_xor_sync(0xffffffffu, acc, 16);
            if ((lane >> 4) == 0) stTop2[d] = __float2half2_rn(acc);
        }
        __syncthreads();   // B2: state(t+1), stTop2(t+1) ready

        // ---- B2..B3: gates(t+1) + pushv(t+1)
        if (wid == 2) {
            float a = g_pgt[sym1 * 64 + lane] * state[lane]
                    + g_pgt[sym1 * 64 + 32 + lane] * state[lane + 32];
            #pragma unroll
            for (int o = 16; o > 0; o >>= 1) a += __shfl_xor_sync(0xffffffffu, a, o);
            if (lane == 0) scal[0] = 1.f / (1.f + __expf(-a));
        } else if (wid == 3) {
            float a = g_ppt[sym1 * 64 + lane] * state[lane]
                    + g_ppt[sym1 * 64 + 32 + lane] * state[lane + 32];
            #pragma unroll
            for (int o = 16; o > 0; o >>= 1) a += __shfl_xor_sync(0xffffffffu, a, o);
            if (lane == 0) scal[1] = 1.f / (1.f + __expf(-a));
        } else if (wid >= 4 && wid < 8) {
            const int d  = (wid - 4) * 16 + (lane & 15);
            const int sb = (lane >> 4) * 32;
            float acc = 0.f;
            #pragma unroll 8
            for (int j = 0; j < 32; j++)
                acc += state[sb + j] * g_pvt[sym1 * 4096 + (sb + j) * 64 + d];
            acc += __shfl_xor_sync(0xffffffffu, acc, 16);
            if ((lane >> 4) == 0) pushv[d] = tanh_fast(acc);
        }
    }

    asm volatile("barrier.cluster.arrive.aligned;" ::: "memory");
    asm volatile("barrier.cluster.wait.aligned;" ::: "memory");
}

extern "C" void kernel_launch(void* const* d_in, const int* in_sizes, int n_in,
                              void* d_out, int out_size)
{
    const int*   seq   = (const int*)  d_in[0];
    const float* Tt    = (const float*)d_in[1];
    const float* Ot    = (const float*)d_in[2];
    const float* pgate = (const float*)d_in[3];
    const float* pop   = (const float*)d_in[4];
    const float* pval  = (const float*)d_in[5];
    const float* initl = (const float*)d_in[6];
    float* out = (float*)d_out;

    cvt_kernel<<<(unsigned)((TOTAL4 + 255) / 256), 256>>>(Tt, Ot);
    tr_kernel<<<(I_ * S_ * D_ + 255) / 256, 256>>>(pgate, pop, pval);
    fpt_kernel<<<2 * B_, NTHREADS>>>(seq, initl, out);
}

// round 8
// speedup vs baseline: 1.1174x; 1.1174x over previous
#include <cuda_runtime.h>
#include <cuda_fp16.h>
#include <cstdint>
#include <math.h>

#define S_    64
#define I_    128
#define NO_   64
#define K_    64
#define D_    64
#define B_    64
#define TLEN_ 256
#define THR_  0.01f
#define NTHREADS 1024

#define WELEM  ((size_t)S_ * I_ * D_ * S_)
#define TOTAL4 (WELEM / 4)
#define OUTN   (B_ * TLEN_ * NO_)

__device__ __half g_Th[WELEM];
__device__ __half g_Oh[WELEM];
__device__ float  g_pvt[I_ * S_ * D_];   // pv transposed: [i][s][d]
__device__ float  g_pgt[I_ * S_];        // push_gate transposed: [i][s]
__device__ float  g_ppt[I_ * S_];        // pop_gate transposed:  [i][s]

__global__ __launch_bounds__(256)
void cvt_kernel(const float* __restrict__ Ts, const float* __restrict__ Os) {
    size_t i = (size_t)blockIdx.x * blockDim.x + threadIdx.x;
    if (i >= TOTAL4) return;
    float4 a = ((const float4*)Ts)[i];
    float4 b = ((const float4*)Os)[i];
    __half2 a0 = __floats2half2_rn(a.x, a.y);
    __half2 a1 = __floats2half2_rn(a.z, a.w);
    __half2 b0 = __floats2half2_rn(b.x, b.y);
    __half2 b1 = __floats2half2_rn(b.z, b.w);
    uint2 ua, ub;
    ua.x = *(unsigned*)&a0; ua.y = *(unsigned*)&a1;
    ub.x = *(unsigned*)&b0; ub.y = *(unsigned*)&b1;
    ((uint2*)g_Th)[i] = ua;
    ((uint2*)g_Oh)[i] = ub;
}

__global__ __launch_bounds__(256)
void tr_kernel(const float* __restrict__ pg, const float* __restrict__ pp,
               const float* __restrict__ pv) {
    int idx = blockIdx.x * blockDim.x + threadIdx.x;
    if (idx < I_ * S_ * D_) {
        int d = idx & 63;
        int s = (idx >> 6) & 63;
        int i = idx >> 12;
        g_pvt[idx] = pv[(s * I_ + i) * D_ + d];
    }
    if (idx < I_ * S_) {
        int s = idx & 63;
        int i = idx >> 6;
        g_pgt[idx] = pg[s * I_ + i];
        g_ppt[idx] = pp[s * I_ + i];
    }
}

__global__ __launch_bounds__(1024)
void zero_kernel(float* __restrict__ o) {
    int i = blockIdx.x * blockDim.x + threadIdx.x;
    if (i < OUTN / 4) ((float4*)o)[i] = make_float4(0.f, 0.f, 0.f, 0.f);
}

// ---------- helpers ----------
__device__ __forceinline__ unsigned int s2u(const void* p) {
    unsigned int a;
    asm("{ .reg .u64 t; cvta.to.shared.u64 t, %1; cvt.u32.u64 %0, t; }" : "=r"(a) : "l"(p));
    return a;
}
__device__ __forceinline__ unsigned int ctarank() {
    unsigned int r; asm("mov.u32 %0, %%cluster_ctarank;" : "=r"(r)); return r;
}
__device__ __forceinline__ void arrive_peer(unsigned int local_bar, unsigned int peer) {
    asm volatile(
        "{ .reg .b32 ra;\n\t"
        "mapa.shared::cluster.u32 ra, %0, %1;\n\t"
        "mbarrier.arrive.release.cluster.shared::cluster.b64 _, [ra]; }"
        :: "r"(local_bar), "r"(peer) : "memory");
}
__device__ __forceinline__ void wait_bar_cluster(unsigned int bar, unsigned int parity) {
    asm volatile(
        "{\n\t.reg .pred P;\n\t"
        "WL%=:\n\t"
        "mbarrier.try_wait.parity.acquire.cluster.shared::cta.b64 P, [%0], %1, 0x989680;\n\t"
        "@P bra.uni WD%=;\n\t"
        "bra.uni WL%=;\n\t"
        "WD%=:\n\t}"
        :: "r"(bar), "r"(parity) : "memory");
}
__device__ __forceinline__ float ld_peer_f32(unsigned int local_addr, unsigned int peer) {
    unsigned int ra, v;
    asm("mapa.shared::cluster.u32 %0, %1, %2;" : "=r"(ra) : "r"(local_addr), "r"(peer));
    asm volatile("ld.shared::cluster.b32 %0, [%1];" : "=r"(v) : "r"(ra) : "memory");
    return __uint_as_float(v);
}
__device__ __forceinline__ float tanh_fast(float x) {
    float y; asm("tanh.approx.f32 %0, %1;" : "=f"(y) : "f"(x)); return y;
}
__device__ __forceinline__ int ld_acq_sh(unsigned int a) {
    int v; asm volatile("ld.acquire.cta.shared.b32 %0, [%1];" : "=r"(v) : "r"(a) : "memory");
    return v;
}
__device__ __forceinline__ void st_rel_sh(unsigned int a, int v) {
    asm volatile("st.release.cta.shared.b32 [%0], %1;" :: "r"(a), "r"(v) : "memory");
}
__device__ __forceinline__ void red_add_f32(float* p, float v) {
    asm volatile("red.global.add.f32 [%0], %1;" :: "l"(p), "f"(v) : "memory");
}

// in-place softmax over 64 values: 8 per lane across an 8-lane group
__device__ __forceinline__ void softmax8(float* a) {
    float m = a[0];
    #pragma unroll
    for (int j = 1; j < 8; j++) m = fmaxf(m, a[j]);
    #pragma unroll
    for (int o = 4; o > 0; o >>= 1) m = fmaxf(m, __shfl_xor_sync(0xffffffffu, m, o, 8));
    float s = 0.f;
    #pragma unroll
    for (int j = 0; j < 8; j++) { a[j] = __expf(a[j] - m); s += a[j]; }
    #pragma unroll
    for (int o = 4; o > 0; o >>= 1) s += __shfl_xor_sync(0xffffffffu, s, o, 8);
    float inv = 1.0f / s;
    #pragma unroll
    for (int j = 0; j < 8; j++) a[j] *= inv;
}

struct __align__(16) Smem {
    unsigned long long bar[2];
    float content[K_ * D_];
    float partT[32 * 64];
    float partO[2][32 * 64];
    float state[S_];
    float pb[2][K_];
    float pushv[D_];
    float wbuf[K_];
    float scal[4];
    float exch[2][64];
    int   seq_s[TLEN_ + 1];
    int   flags[TLEN_ + 1];
    float trace_state[TLEN_ + 1][S_];
    unsigned int trace_top[TLEN_ + 1][D_];   // half2 bits of stack_top
};

// dual-row contraction: rows ra/rb of W (fp16 slices), weights from trace_top row tt,
// output (post-softmax, pre-state-weight) in fa/fb
__device__ __forceinline__ void contract2(const uint4* __restrict__ A4,
                                          const uint4* __restrict__ B4,
                                          const unsigned int* __restrict__ tt,
                                          int lane, float* fa, float* fb)
{
    const int lr = lane >> 3;
    #pragma unroll
    for (int j = 0; j < 8; j++) { fa[j] = 0.f; fb[j] = 0.f; }
    const __half2 hz = __float2half2_rn(0.f);
    #pragma unroll
    for (int chunk = 0; chunk < 2; chunk++) {
        __half2 hA[4] = {hz, hz, hz, hz};
        __half2 hB[4] = {hz, hz, hz, hz};
        #pragma unroll
        for (int i = 0; i < 8; i++) {
            const int ii = chunk * 8 + i;
            unsigned int tb = tt[ii * 4 + lr];
            const __half2 td2 = *(__half2*)&tb;
            uint4 v = A4[ii * 32 + lane];
            hA[0] = __hfma2(td2, *(__half2*)&v.x, hA[0]);
            hA[1] = __hfma2(td2, *(__half2*)&v.y, hA[1]);
            hA[2] = __hfma2(td2, *(__half2*)&v.z, hA[2]);
            hA[3] = __hfma2(td2, *(__half2*)&v.w, hA[3]);
            uint4 u = B4[ii * 32 + lane];
            hB[0] = __hfma2(td2, *(__half2*)&u.x, hB[0]);
            hB[1] = __hfma2(td2, *(__half2*)&u.y, hB[1]);
            hB[2] = __hfma2(td2, *(__half2*)&u.z, hB[2]);
            hB[3] = __hfma2(td2, *(__half2*)&u.w, hB[3]);
        }
        #pragma unroll
        for (int c = 0; c < 4; c++) {
            float2 f = __half22float2(hA[c]);
            fa[2 * c] += f.x; fa[2 * c + 1] += f.y;
            f = __half22float2(hB[c]);
            fb[2 * c] += f.x; fb[2 * c + 1] += f.y;
        }
    }
    #pragma unroll
    for (int j = 0; j < 8; j++) {
        fa[j] += __shfl_xor_sync(0xffffffffu, fa[j], 8);
        fa[j] += __shfl_xor_sync(0xffffffffu, fa[j], 16);
        fb[j] += __shfl_xor_sync(0xffffffffu, fb[j], 8);
        fb[j] += __shfl_xor_sync(0xffffffffu, fb[j], 16);
    }
    softmax8(fa);
    softmax8(fb);
}

__global__ __launch_bounds__(NTHREADS, 1) __cluster_dims__(2, 1, 1)
void fpt_kernel(const int*   __restrict__ seq,
                const float* __restrict__ initl,
                float*       __restrict__ out)
{
    extern __shared__ char smem_raw[];
    Smem* sm = (Smem*)smem_raw;

    const int tid   = threadIdx.x;
    const int wid   = tid >> 5;
    const int lane  = tid & 31;
    const int lc    = lane & 7;
    const int lr    = lane >> 3;
    const unsigned int rank = ctarank();
    const unsigned int peer = rank ^ 1u;
    const int b     = blockIdx.x >> 1;

    // ---- init (all threads)
    if (tid < S_) sm->wbuf[tid] = initl[tid];
    for (int e = tid; e <= TLEN_; e += NTHREADS) {
        sm->seq_s[e] = (e < TLEN_) ? seq[b * TLEN_ + e] : 0;
        sm->flags[e] = 0;
    }
    for (int e = tid; e < K_ * D_; e += NTHREADS) sm->content[e] = 0.f;
    if (tid < K_) {
        sm->pb[0][tid] = (tid == 0) ? 1.f : 0.f;
        sm->pb[1][tid] = 0.f;
    }
    if (tid < D_) sm->trace_top[0][tid] = 0u;   // stack_top(0) = 0
    __syncthreads();
    if (tid == 0) {
        float m = -1e30f;
        for (int i = 0; i < S_; i++) m = fmaxf(m, sm->wbuf[i]);
        float ssum = 0.f;
        for (int i = 0; i < S_; i++) { float e = expf(sm->wbuf[i] - m); sm->pushv[i] = e; ssum += e; }
        sm->scal[2] = ssum;
        asm volatile("mbarrier.init.shared.b64 [%0], 1;" :: "r"(s2u(&sm->bar[0])) : "memory");
        asm volatile("mbarrier.init.shared.b64 [%0], 1;" :: "r"(s2u(&sm->bar[1])) : "memory");
    }
    __syncthreads();
    if (tid < S_) {
        float st0 = sm->pushv[tid] / sm->scal[2];
        sm->state[tid] = st0;
        sm->trace_state[0][tid] = st0;
    }
    __syncthreads();

    // prologue: gates(0), pushv(0) with transposed arrays
    {
        const int sym0 = sm->seq_s[0];
        if (wid == 2) {
            float a = g_pgt[sym0 * 64 + lane] * sm->state[lane]
                    + g_pgt[sym0 * 64 + 32 + lane] * sm->state[lane + 32];
            #pragma unroll
            for (int o = 16; o > 0; o >>= 1) a += __shfl_xor_sync(0xffffffffu, a, o);
            if (lane == 0) sm->scal[0] = 1.f / (1.f + __expf(-a));
        } else if (wid == 3) {
            float a = g_ppt[sym0 * 64 + lane] * sm->state[lane]
                    + g_ppt[sym0 * 64 + 32 + lane] * sm->state[lane + 32];
            #pragma unroll
            for (int o = 16; o > 0; o >>= 1) a += __shfl_xor_sync(0xffffffffu, a, o);
            if (lane == 0) sm->scal[1] = 1.f / (1.f + __expf(-a));
        } else if (wid >= 8 && wid < 12) {
            const int d  = (wid - 8) * 16 + (lane & 15);
            const int sb = (lane >> 4) * 32;
            float acc = 0.f;
            #pragma unroll 8
            for (int j = 0; j < 32; j++)
                acc += sm->state[sb + j] * g_pvt[sym0 * 4096 + (sb + j) * 64 + d];
            acc += __shfl_xor_sync(0xffffffffu, acc, 16);
            if ((lane >> 4) == 0) sm->pushv[d] = tanh_fast(acc);
        }
    }
    __syncthreads();

    asm volatile("barrier.cluster.arrive.aligned;" ::: "memory");
    asm volatile("barrier.cluster.wait.aligned;" ::: "memory");

    const unsigned int bar_u[2]  = { s2u(&sm->bar[0]), s2u(&sm->bar[1]) };
    const unsigned int exch_u    = s2u(&sm->exch[0][0]);
    const unsigned int flags_u   = s2u(&sm->flags[0]);

    if (wid < 16) {
        // ================= T path: the recurrence =================
        const int r0 = (int)rank * 32 + wid * 2;
        const int r1 = r0 + 1;
        const int rl0 = wid * 2, rl1 = rl0 + 1;

        for (int t = 0; t < TLEN_; t++) {
            const int sym  = sm->seq_s[t];
            const int sym1 = sm->seq_s[t + 1];
            const int p    = t & 1;
            const int np   = p ^ 1;
            const unsigned int par = (unsigned int)(t >> 1) & 1u;

            asm volatile("bar.sync 2, 512;" ::: "memory");     // A: trace[t], scal, pushv, pb[p] ready
            if (tid == 0) st_rel_sh(flags_u + 4u * t, 1);      // publish step t to O-warps

            // phase2-T: 2 rows per warp
            {
                float fa[8], fb[8];
                contract2((const uint4*)(g_Th + (size_t)(r0 * I_ + sym) * 4096),
                          (const uint4*)(g_Th + (size_t)(r1 * I_ + sym) * 4096),
                          sm->trace_top[t], lane, fa, fb);
                const float s0 = sm->state[r0];
                const float s1 = sm->state[r1];
                if (lr == 0) {
                    float4 w;
                    w.x = s0 * fa[0]; w.y = s0 * fa[1]; w.z = s0 * fa[2]; w.w = s0 * fa[3];
                    *(float4*)&sm->partT[rl0 * 64 + lc * 8]     = w;
                    w.x = s0 * fa[4]; w.y = s0 * fa[5]; w.z = s0 * fa[6]; w.w = s0 * fa[7];
                    *(float4*)&sm->partT[rl0 * 64 + lc * 8 + 4] = w;
                    w.x = s1 * fb[0]; w.y = s1 * fb[1]; w.z = s1 * fb[2]; w.w = s1 * fb[3];
                    *(float4*)&sm->partT[rl1 * 64 + lc * 8]     = w;
                    w.x = s1 * fb[4]; w.y = s1 * fb[5]; w.z = s1 * fb[6]; w.w = s1 * fb[7];
                    *(float4*)&sm->partT[rl1 * 64 + lc * 8 + 4] = w;
                }
            }
            asm volatile("bar.sync 2, 512;" ::: "memory");     // B1: partT ready

            if (tid < 64) {
                // reduce + cluster exchange of new_state
                float mine = 0.f;
                #pragma unroll
                for (int r = 0; r < 32; r++) mine += sm->partT[r * 64 + tid];
                sm->exch[p][tid] = mine;
                asm volatile("bar.sync 1, 64;" ::: "memory");
                if (tid == 0) arrive_peer(bar_u[p], peer);
                wait_bar_cluster(bar_u[p], par);
                float pv_ = ld_peer_f32(exch_u + (unsigned int)(p * 64 + tid) * 4u, peer);
                float ns = mine + pv_;
                sm->state[tid] = ns;
                sm->trace_state[t + 1][tid] = ns;
            } else if (wid == 15) {
                // pointer update
                const float pushs = sm->scal[0];
                const float pops  = sm->scal[1];
                const int i0 = lane * 2;
                float p0 = sm->pb[p][i0], p1 = sm->pb[p][i0 + 1];
                float d1 = __shfl_down_sync(0xffffffffu, p0, 1);
                if (lane == 31) d1 = 0.f;
                if (pops > THR_) {
                    p0 = pops * p1 + (1.f - pops) * p0;
                    p1 = pops * d1 + (1.f - pops) * p1;
                }
                float u0 = __shfl_up_sync(0xffffffffu, p1, 1);
                if (lane == 0) u0 = 0.f;
                float q0 = pushs * u0 + (1.f - pushs) * p0;
                float q1 = pushs * p0 + (1.f - pushs) * p1;
                sm->wbuf[i0] = q0; sm->wbuf[i0 + 1] = q1;
                sm->pb[np][i0]     = (pushs > THR_) ? q0 : p0;
                sm->pb[np][i0 + 1] = (pushs > THR_) ? q1 : p1;
            }
            asm volatile("bar.sync 2, 512;" ::: "memory");     // B2: state(t+1), pb[np], wbuf ready

            // content update
            {
                const float pushs = sm->scal[0];
                if (pushs > THR_) {
                    #pragma unroll
                    for (int i = 0; i < 8; i++) {
                        int e = tid + 512 * i;
                        int k = e >> 6, d = e & 63;
                        float wk = sm->wbuf[k];
                        sm->content[e] = sm->content[e] * (1.f - wk) + sm->pushv[d] * wk;
                    }
                }
            }
            asm volatile("bar.sync 2, 512;" ::: "memory");     // B3: content(t+1) committed

            // tail: stack_top(t+1), gates(t+1), pushv(t+1)
            if (wid == 2) {
                float a = g_pgt[sym1 * 64 + lane] * sm->state[lane]
                        + g_pgt[sym1 * 64 + 32 + lane] * sm->state[lane + 32];
                #pragma unroll
                for (int o = 16; o > 0; o >>= 1) a += __shfl_xor_sync(0xffffffffu, a, o);
                if (lane == 0) sm->scal[0] = 1.f / (1.f + __expf(-a));
            } else if (wid == 3) {
                float a = g_ppt[sym1 * 64 + lane] * sm->state[lane]
                        + g_ppt[sym1 * 64 + 32 + lane] * sm->state[lane + 32];
                #pragma unroll
                for (int o = 16; o > 0; o >>= 1) a += __shfl_xor_sync(0xffffffffu, a, o);
                if (lane == 0) sm->scal[1] = 1.f / (1.f + __expf(-a));
            } else if (wid >= 4 && wid < 8) {
                const int d  = (wid - 4) * 16 + (lane & 15);
                const int kb = (lane >> 4) * 32;
                float acc = 0.f;
                #pragma unroll 8
                for (int j = 0; j < 32; j++)
                    acc += sm->pb[np][kb + j] * sm->content[(kb + j) * D_ + d];
                acc += __shfl_xor_sync(0xffffffffu, acc, 16);
                if ((lane >> 4) == 0) {
                    __half2 h = __float2half2_rn(acc);
                    sm->trace_top[t + 1][d] = *(unsigned int*)&h;
                }
            } else if (wid >= 8 && wid < 12) {
                const int d  = (wid - 8) * 16 + (lane & 15);
                const int sb = (lane >> 4) * 32;
                float acc = 0.f;
                #pragma unroll 8
                for (int j = 0; j < 32; j++)
                    acc += sm->state[sb + j] * g_pvt[sym1 * 4096 + (sb + j) * 64 + d];
                acc += __shfl_xor_sync(0xffffffffu, acc, 16);
                if ((lane >> 4) == 0) sm->pushv[d] = tanh_fast(acc);
            }
        }
    } else {
        // ================= O path: lagging output consumer =================
        const int ow  = wid - 16;
        const int r0  = (int)rank * 32 + ow * 2;
        const int r1  = r0 + 1;
        const int rl0 = ow * 2, rl1 = rl0 + 1;
        const int otid = tid - 512;

        for (int t = 0; t < TLEN_; t++) {
            while (ld_acq_sh(flags_u + 4u * t) == 0) { }
            const int sym = sm->seq_s[t];
            const int pp2 = t & 1;

            float fa[8], fb[8];
            contract2((const uint4*)(g_Oh + (size_t)(r0 * I_ + sym) * 4096),
                      (const uint4*)(g_Oh + (size_t)(r1 * I_ + sym) * 4096),
                      sm->trace_top[t], lane, fa, fb);
            const float s0 = sm->trace_state[t][r0];
            const float s1 = sm->trace_state[t][r1];
            if (lr == 0) {
                float4 w;
                w.x = s0 * fa[0]; w.y = s0 * fa[1]; w.z = s0 * fa[2]; w.w = s0 * fa[3];
                *(float4*)&sm->partO[pp2][rl0 * 64 + lc * 8]     = w;
                w.x = s0 * fa[4]; w.y = s0 * fa[5]; w.z = s0 * fa[6]; w.w = s0 * fa[7];
                *(float4*)&sm->partO[pp2][rl0 * 64 + lc * 8 + 4] = w;
                w.x = s1 * fb[0]; w.y = s1 * fb[1]; w.z = s1 * fb[2]; w.w = s1 * fb[3];
                *(float4*)&sm->partO[pp2][rl1 * 64 + lc * 8]     = w;
                w.x = s1 * fb[4]; w.y = s1 * fb[5]; w.z = s1 * fb[6]; w.w = s1 * fb[7];
                *(float4*)&sm->partO[pp2][rl1 * 64 + lc * 8 + 4] = w;
            }
            asm volatile("bar.sync 3, 512;" ::: "memory");
            if (otid < 64) {
                float m = 0.f;
                #pragma unroll
                for (int r = 0; r < 32; r++) m += sm->partO[pp2][r * 64 + otid];
                red_add_f32(&out[((size_t)b * TLEN_ + t) * NO_ + otid], m);
            }
        }
    }

    asm volatile("barrier.cluster.arrive.aligned;" ::: "memory");
    asm volatile("barrier.cluster.wait.aligned;" ::: "memory");
}

extern "C" void kernel_launch(void* const* d_in, const int* in_sizes, int n_in,
                              void* d_out, int out_size)
{
    const int*   seq   = (const int*)  d_in[0];
    const float* Tt    = (const float*)d_in[1];
    const float* Ot    = (const float*)d_in[2];
    const float* pgate = (const float*)d_in[3];
    const float* pop   = (const float*)d_in[4];
    const float* pval  = (const float*)d_in[5];
    const float* initl = (const float*)d_in[6];
    float* out = (float*)d_out;

    cudaFuncSetAttribute(fpt_kernel, cudaFuncAttributeMaxDynamicSharedMemorySize,
                         (int)sizeof(Smem));

    cvt_kernel<<<(unsigned)((TOTAL4 + 255) / 256), 256>>>(Tt, Ot);
    tr_kernel<<<(I_ * S_ * D_ + 255) / 256, 256>>>(pgate, pop, pval);
    zero_kernel<<<(OUTN / 4 + 1023) / 1024, 1024>>>(out);
    fpt_kernel<<<2 * B_, NTHREADS, sizeof(Smem)>>>(seq, initl, out);
}

// round 9
// speedup vs baseline: 1.2348x; 1.1051x over previous
#include <cuda_runtime.h>
#include <cuda_fp16.h>
#include <cstdint>
#include <math.h>

#define S_    64
#define I_    128
#define NO_   64
#define K_    64
#define D_    64
#define B_    64
#define TLEN_ 256
#define THR_  0.01f
#define NTHREADS 1024

#define WELEM  ((size_t)S_ * I_ * D_ * S_)
#define TOTAL4 (WELEM / 4)

__device__ __half g_Th[WELEM];
__device__ __half g_Oh[WELEM];
__device__ float  g_pvt[I_ * S_ * D_];   // pv transposed: [i][s][d]
__device__ float  g_pgt[I_ * S_];        // push_gate transposed: [i][s]
__device__ float  g_ppt[I_ * S_];        // pop_gate transposed:  [i][s]

__global__ __launch_bounds__(256)
void cvt_kernel(const float* __restrict__ Ts, const float* __restrict__ Os) {
    size_t i = (size_t)blockIdx.x * blockDim.x + threadIdx.x;
    if (i >= TOTAL4) return;
    float4 a = ((const float4*)Ts)[i];
    float4 b = ((const float4*)Os)[i];
    __half2 a0 = __floats2half2_rn(a.x, a.y);
    __half2 a1 = __floats2half2_rn(a.z, a.w);
    __half2 b0 = __floats2half2_rn(b.x, b.y);
    __half2 b1 = __floats2half2_rn(b.z, b.w);
    uint2 ua, ub;
    ua.x = *(unsigned*)&a0; ua.y = *(unsigned*)&a1;
    ub.x = *(unsigned*)&b0; ub.y = *(unsigned*)&b1;
    ((uint2*)g_Th)[i] = ua;
    ((uint2*)g_Oh)[i] = ub;
}

__global__ __launch_bounds__(256)
void tr_kernel(const float* __restrict__ pg, const float* __restrict__ pp,
               const float* __restrict__ pv) {
    int idx = blockIdx.x * blockDim.x + threadIdx.x;
    if (idx < I_ * S_ * D_) {
        int d = idx & 63;
        int s = (idx >> 6) & 63;
        int i = idx >> 12;
        g_pvt[idx] = pv[(s * I_ + i) * D_ + d];
    }
    if (idx < I_ * S_) {
        int s = idx & 63;
        int i = idx >> 6;
        g_pgt[idx] = pg[s * I_ + i];
        g_ppt[idx] = pp[s * I_ + i];
    }
}

// ---------- helpers ----------
__device__ __forceinline__ unsigned int s2u(const void* p) {
    unsigned int a;
    asm("{ .reg .u64 t; cvta.to.shared.u64 t, %1; cvt.u32.u64 %0, t; }" : "=r"(a) : "l"(p));
    return a;
}
__device__ __forceinline__ unsigned int ctarank() {
    unsigned int r; asm("mov.u32 %0, %%cluster_ctarank;" : "=r"(r)); return r;
}
__device__ __forceinline__ float tanh_fast(float x) {
    float y; asm("tanh.approx.f32 %0, %1;" : "=f"(y) : "f"(x)); return y;
}
// release-store (cluster scope) into our own smem flag
__device__ __forceinline__ void st_rel_flag(unsigned int a, int v) {
    asm volatile("st.release.cluster.shared::cta.b32 [%0], %1;" :: "r"(a), "r"(v) : "memory");
}
// acquire-load of peer CTA's smem word
__device__ __forceinline__ int ld_acq_remote(unsigned int laddr, unsigned int peer) {
    unsigned int ra; int v;
    asm("mapa.shared::cluster.u32 %0, %1, %2;" : "=r"(ra) : "r"(laddr), "r"(peer));
    asm volatile("ld.acquire.cluster.shared::cluster.b32 %0, [%1];" : "=r"(v) : "r"(ra) : "memory");
    return v;
}
__device__ __forceinline__ unsigned int ld_remote_u32(unsigned int laddr, unsigned int peer) {
    unsigned int ra, v;
    asm("mapa.shared::cluster.u32 %0, %1, %2;" : "=r"(ra) : "r"(laddr), "r"(peer));
    asm volatile("ld.shared::cluster.b32 %0, [%1];" : "=r"(v) : "r"(ra) : "memory");
    return v;
}

// in-place softmax over 64 values: 8 per lane across an 8-lane group
__device__ __forceinline__ void softmax8(float* a) {
    float m = a[0];
    #pragma unroll
    for (int j = 1; j < 8; j++) m = fmaxf(m, a[j]);
    #pragma unroll
    for (int o = 4; o > 0; o >>= 1) m = fmaxf(m, __shfl_xor_sync(0xffffffffu, m, o, 8));
    float s = 0.f;
    #pragma unroll
    for (int j = 0; j < 8; j++) { a[j] = __expf(a[j] - m); s += a[j]; }
    #pragma unroll
    for (int o = 4; o > 0; o >>= 1) s += __shfl_xor_sync(0xffffffffu, s, o, 8);
    float inv = 1.0f / s;
    #pragma unroll
    for (int j = 0; j < 8; j++) a[j] *= inv;
}

struct __align__(16) Smem {
    float    content[2][K_ * D_];          // 32 KB  (CTA0)
    float    part[64 * 64];                // 16 KB  (partT on CTA0 / partO on CTA1)
    float    trace_state[TLEN_ + 1][S_];   // 65.8 KB (CTA0)
    unsigned trace_top[TLEN_ + 1][D_];     // 65.8 KB (CTA0; half2 bits of stack_top)
    int      flags[TLEN_ + 1];
    int      seq_s[TLEN_ + 1];
    float    pb[2][K_];
    float    pv2[2][D_];
    float    wbuf[K_];
    float    mbuf[K_];
    float    scal[8];
    float    tstate_l[S_];                 // CTA1 pull buffers
    unsigned ttop_l[D_];
};

// dual-row contraction: rows A4/B4 (fp16 slices), weights tt (half2 bits per d),
// result post-softmax in fa/fb (8 cols per lane, valid in all lanes of 8-group)
__device__ __forceinline__ void contract2(const uint4* __restrict__ A4,
                                          const uint4* __restrict__ B4,
                                          const unsigned int* __restrict__ tt,
                                          int lane, float* fa, float* fb)
{
    const int lr = lane >> 3;
    #pragma unroll
    for (int j = 0; j < 8; j++) { fa[j] = 0.f; fb[j] = 0.f; }
    const __half2 hz = __float2half2_rn(0.f);
    #pragma unroll
    for (int chunk = 0; chunk < 2; chunk++) {
        __half2 hA[4] = {hz, hz, hz, hz};
        __half2 hB[4] = {hz, hz, hz, hz};
        #pragma unroll
        for (int i = 0; i < 8; i++) {
            const int ii = chunk * 8 + i;
            unsigned int tb = tt[ii * 4 + lr];
            const __half2 td2 = *(__half2*)&tb;
            uint4 v = A4[ii * 32 + lane];
            hA[0] = __hfma2(td2, *(__half2*)&v.x, hA[0]);
            hA[1] = __hfma2(td2, *(__half2*)&v.y, hA[1]);
            hA[2] = __hfma2(td2, *(__half2*)&v.z, hA[2]);
            hA[3] = __hfma2(td2, *(__half2*)&v.w, hA[3]);
            uint4 u = B4[ii * 32 + lane];
            hB[0] = __hfma2(td2, *(__half2*)&u.x, hB[0]);
            hB[1] = __hfma2(td2, *(__half2*)&u.y, hB[1]);
            hB[2] = __hfma2(td2, *(__half2*)&u.z, hB[2]);
            hB[3] = __hfma2(td2, *(__half2*)&u.w, hB[3]);
        }
        #pragma unroll
        for (int c = 0; c < 4; c++) {
            float2 f = __half22float2(hA[c]);
            fa[2 * c] += f.x; fa[2 * c + 1] += f.y;
            f = __half22float2(hB[c]);
            fb[2 * c] += f.x; fb[2 * c + 1] += f.y;
        }
    }
    #pragma unroll
    for (int j = 0; j < 8; j++) {
        fa[j] += __shfl_xor_sync(0xffffffffu, fa[j], 8);
        fa[j] += __shfl_xor_sync(0xffffffffu, fa[j], 16);
        fb[j] += __shfl_xor_sync(0xffffffffu, fb[j], 8);
        fb[j] += __shfl_xor_sync(0xffffffffu, fb[j], 16);
    }
    softmax8(fa);
    softmax8(fb);
}

__global__ __launch_bounds__(NTHREADS, 1) __cluster_dims__(2, 1, 1)
void fpt_kernel(const int*   __restrict__ seq,
                const float* __restrict__ initl,
                float*       __restrict__ out)
{
    extern __shared__ char smem_raw[];
    Smem* sm = (Smem*)smem_raw;

    const int tid  = threadIdx.x;
    const int wid  = tid >> 5;
    const int lane = tid & 31;
    const int lc   = lane & 7;
    const int lr   = lane >> 3;
    const unsigned int rank = ctarank();
    const int b    = blockIdx.x >> 1;

    // ---- init (both ranks)
    if (tid < S_) sm->wbuf[tid] = initl[tid];
    for (int e = tid; e <= TLEN_; e += NTHREADS) {
        sm->seq_s[e] = (e < TLEN_) ? seq[b * TLEN_ + e] : 0;
        sm->flags[e] = 0;
    }
    for (int e = tid; e < K_ * D_; e += NTHREADS) sm->content[0][e] = 0.f;
    if (tid < K_) { sm->pb[0][tid] = (tid == 0) ? 1.f : 0.f; sm->pb[1][tid] = 0.f; }
    if (tid < D_) sm->trace_top[0][tid] = 0u;
    __syncthreads();
    if (tid == 0) {
        float m = -1e30f;
        for (int i = 0; i < S_; i++) m = fmaxf(m, sm->wbuf[i]);
        float ssum = 0.f;
        for (int i = 0; i < S_; i++) { float e = expf(sm->wbuf[i] - m); sm->mbuf[i] = e; ssum += e; }
        sm->scal[2] = ssum;
    }
    __syncthreads();
    if (tid < S_) sm->trace_state[0][tid] = sm->mbuf[tid] / sm->scal[2];
    __syncthreads();

    // prologue (rank 0 only): gates(0) -> scal[0..1], pushv(0) -> pv2[0]
    if (rank == 0) {
        const int sym0 = sm->seq_s[0];
        if (wid == 2) {
            float a = g_pgt[sym0 * 64 + lane] * sm->trace_state[0][lane]
                    + g_pgt[sym0 * 64 + 32 + lane] * sm->trace_state[0][lane + 32];
            #pragma unroll
            for (int o = 16; o > 0; o >>= 1) a += __shfl_xor_sync(0xffffffffu, a, o);
            if (lane == 0) sm->scal[0] = 1.f / (1.f + __expf(-a));
        } else if (wid == 3) {
            float a = g_ppt[sym0 * 64 + lane] * sm->trace_state[0][lane]
                    + g_ppt[sym0 * 64 + 32 + lane] * sm->trace_state[0][lane + 32];
            #pragma unroll
            for (int o = 16; o > 0; o >>= 1) a += __shfl_xor_sync(0xffffffffu, a, o);
            if (lane == 0) sm->scal[1] = 1.f / (1.f + __expf(-a));
        } else if (wid >= 6 && wid < 10) {
            const int d  = (wid - 6) * 16 + (lane & 15);
            const int sb = (lane >> 4) * 32;
            float acc = 0.f;
            #pragma unroll 8
            for (int j = 0; j < 32; j++)
                acc += sm->trace_state[0][sb + j] * g_pvt[sym0 * 4096 + (sb + j) * 64 + d];
            acc += __shfl_xor_sync(0xffffffffu, acc, 16);
            if ((lane >> 4) == 0) sm->pv2[0][d] = tanh_fast(acc);
        }
        __syncthreads();
    }

    // cluster sync: CTA0's flags zeroed + init complete before CTA1 polls
    asm volatile("barrier.cluster.arrive.aligned;" ::: "memory");
    asm volatile("barrier.cluster.wait.aligned;" ::: "memory");

    const unsigned int flags_u = s2u(&sm->flags[0]);

    if (rank == 0) {
        // ===================== recurrence CTA =====================
        const int r0 = wid * 2, r1 = r0 + 1;
        int cb = 0;

        for (int t = 0; t < TLEN_; t++) {
            const int sym  = sm->seq_s[t];
            const int sym1 = sm->seq_s[t + 1];
            const int pp   = t & 1;
            const int pvp  = t & 1;

            if (tid == 0) st_rel_flag(flags_u + 4u * t, 1);   // publish step t
            const float pushs = sm->scal[0];
            const float pops  = sm->scal[1];

            // phase-2: T contraction, 2 rows per warp (64 rows total)
            {
                float fa[8], fb[8];
                contract2((const uint4*)(g_Th + (size_t)(r0 * I_ + sym) * 4096),
                          (const uint4*)(g_Th + (size_t)(r1 * I_ + sym) * 4096),
                          sm->trace_top[t], lane, fa, fb);
                const float s0 = sm->trace_state[t][r0];
                const float s1 = sm->trace_state[t][r1];
                if (lr == 0) {
                    float4 w;
                    w.x = s0 * fa[0]; w.y = s0 * fa[1]; w.z = s0 * fa[2]; w.w = s0 * fa[3];
                    *(float4*)&sm->part[r0 * 64 + lc * 8]     = w;
                    w.x = s0 * fa[4]; w.y = s0 * fa[5]; w.z = s0 * fa[6]; w.w = s0 * fa[7];
                    *(float4*)&sm->part[r0 * 64 + lc * 8 + 4] = w;
                    w.x = s1 * fb[0]; w.y = s1 * fb[1]; w.z = s1 * fb[2]; w.w = s1 * fb[3];
                    *(float4*)&sm->part[r1 * 64 + lc * 8]     = w;
                    w.x = s1 * fb[4]; w.y = s1 * fb[5]; w.z = s1 * fb[6]; w.w = s1 * fb[7];
                    *(float4*)&sm->part[r1 * 64 + lc * 8 + 4] = w;
                }
            }
            __syncthreads();   // B1

            if (tid < 64) {
                // local state reduction over all 64 rows
                float ns = 0.f;
                #pragma unroll
                for (int r = 0; r < 64; r++) ns += sm->part[r * 64 + tid];
                sm->trace_state[t + 1][tid] = ns;
            } else if (wid == 30) {
                // pointer update + mbuf/c for the stack_top trick
                const int i0 = lane * 2;
                float p0 = sm->pb[pp][i0], p1 = sm->pb[pp][i0 + 1];
                float d1 = __shfl_down_sync(0xffffffffu, p0, 1);
                if (lane == 31) d1 = 0.f;
                if (pops > THR_) {
                    p0 = pops * p1 + (1.f - pops) * p0;
                    p1 = pops * d1 + (1.f - pops) * p1;
                }
                float u0 = __shfl_up_sync(0xffffffffu, p1, 1);
                if (lane == 0) u0 = 0.f;
                float q0 = pushs * u0 + (1.f - pushs) * p0;
                float q1 = pushs * p0 + (1.f - pushs) * p1;
                sm->wbuf[i0] = q0; sm->wbuf[i0 + 1] = q1;
                const bool push = pushs > THR_;
                float n0 = push ? q0 : p0;
                float n1 = push ? q1 : p1;
                sm->pb[pp ^ 1][i0] = n0; sm->pb[pp ^ 1][i0 + 1] = n1;
                sm->mbuf[i0]     = push ? q0 * (1.f - q0) : n0;
                sm->mbuf[i0 + 1] = push ? q1 * (1.f - q1) : n1;
                float cp = push ? (q0 * q0 + q1 * q1) : 0.f;
                #pragma unroll
                for (int o = 16; o > 0; o >>= 1) cp += __shfl_xor_sync(0xffffffffu, cp, o);
                if (lane == 0) sm->scal[3] = cp;
            }
            __syncthreads();   // B2

            // B2..B3: stack_top(t+1) trick | gates(t+1) | pushv(t+1) | content update
            if (wid < 4) {
                const int d  = wid * 16 + (lane & 15);
                const int kb = (lane >> 4) * 32;
                float acc = 0.f;
                #pragma unroll 8
                for (int j = 0; j < 32; j++)
                    acc += sm->mbuf[kb + j] * sm->content[cb][(kb + j) * 64 + d];
                acc += __shfl_xor_sync(0xffffffffu, acc, 16);
                if ((lane >> 4) == 0) {
                    float top = acc + sm->scal[3] * sm->pv2[pvp][d];
                    __half2 h = __float2half2_rn(top);
                    sm->trace_top[t + 1][d] = *(unsigned int*)&h;
                }
            } else if (wid == 4) {
                float a = g_pgt[sym1 * 64 + lane] * sm->trace_state[t + 1][lane]
                        + g_pgt[sym1 * 64 + 32 + lane] * sm->trace_state[t + 1][lane + 32];
                #pragma unroll
                for (int o = 16; o > 0; o >>= 1) a += __shfl_xor_sync(0xffffffffu, a, o);
                if (lane == 0) sm->scal[0] = 1.f / (1.f + __expf(-a));
            } else if (wid == 5) {
                float a = g_ppt[sym1 * 64 + lane] * sm->trace_state[t + 1][lane]
                        + g_ppt[sym1 * 64 + 32 + lane] * sm->trace_state[t + 1][lane + 32];
                #pragma unroll
                for (int o = 16; o > 0; o >>= 1) a += __shfl_xor_sync(0xffffffffu, a, o);
                if (lane == 0) sm->scal[1] = 1.f / (1.f + __expf(-a));
            } else if (wid >= 6 && wid < 10) {
                const int d  = (wid - 6) * 16 + (lane & 15);
                const int sb = (lane >> 4) * 32;
                float acc = 0.f;
                #pragma unroll 8
                for (int j = 0; j < 32; j++)
                    acc += sm->trace_state[t + 1][sb + j] * g_pvt[sym1 * 4096 + (sb + j) * 64 + d];
                acc += __shfl_xor_sync(0xffffffffu, acc, 16);
                if ((lane >> 4) == 0) sm->pv2[pvp ^ 1][d] = tanh_fast(acc);
            } else if (wid >= 16) {
                if (pushs > THR_) {
                    const int tidc = tid - 512;
                    #pragma unroll
                    for (int i = 0; i < 8; i++) {
                        int e = tidc + 512 * i;
                        int k = e >> 6, d = e & 63;
                        float wk = sm->wbuf[k];
                        sm->content[cb ^ 1][e] =
                            sm->content[cb][e] * (1.f - wk) + sm->pv2[pvp][d] * wk;
                    }
                }
            }
            cb ^= (pushs > THR_) ? 1 : 0;
            __syncthreads();   // B3 / next loop top
        }
    } else {
        // ===================== output CTA (lagging consumer) =====================
        const int r0 = wid * 2, r1 = r0 + 1;
        const unsigned int peer = 0u;

        for (int t = 0; t < TLEN_; t++) {
            if (tid == 0) {
                while (ld_acq_remote(flags_u + 4u * t, peer) == 0) { }
            }
            __syncthreads();   // P0: flag(t) observed
            if (tid < 64) {
                unsigned int v = ld_remote_u32(s2u(&sm->trace_state[t][tid]), peer);
                sm->tstate_l[tid] = __uint_as_float(v);
            } else if (tid < 128) {
                sm->ttop_l[tid - 64] = ld_remote_u32(s2u(&sm->trace_top[t][tid - 64]), peer);
            }
            __syncthreads();   // P1: trace pulled

            const int sym = sm->seq_s[t];
            float fa[8], fb[8];
            contract2((const uint4*)(g_Oh + (size_t)(r0 * I_ + sym) * 4096),
                      (const uint4*)(g_Oh + (size_t)(r1 * I_ + sym) * 4096),
                      sm->ttop_l, lane, fa, fb);
            const float s0 = sm->tstate_l[r0];
            const float s1 = sm->tstate_l[r1];
            if (lr == 0) {
                float4 w;
                w.x = s0 * fa[0]; w.y = s0 * fa[1]; w.z = s0 * fa[2]; w.w = s0 * fa[3];
                *(float4*)&sm->part[r0 * 64 + lc * 8]     = w;
                w.x = s0 * fa[4]; w.y = s0 * fa[5]; w.z = s0 * fa[6]; w.w = s0 * fa[7];
                *(float4*)&sm->part[r0 * 64 + lc * 8 + 4] = w;
                w.x = s1 * fb[0]; w.y = s1 * fb[1]; w.z = s1 * fb[2]; w.w = s1 * fb[3];
                *(float4*)&sm->part[r1 * 64 + lc * 8]     = w;
                w.x = s1 * fb[4]; w.y = s1 * fb[5]; w.z = s1 * fb[6]; w.w = s1 * fb[7];
                *(float4*)&sm->part[r1 * 64 + lc * 8 + 4] = w;
            }
            __syncthreads();   // P2: partO ready

            if (tid < 64) {
                float m = 0.f;
                #pragma unroll
                for (int r = 0; r < 64; r++) m += sm->part[r * 64 + tid];
                out[((size_t)b * TLEN_ + t) * NO_ + tid] = m;
            }
        }
    }

    asm volatile("barrier.cluster.arrive.aligned;" ::: "memory");
    asm volatile("barrier.cluster.wait.aligned;" ::: "memory");
}

extern "C" void kernel_launch(void* const* d_in, const int* in_sizes, int n_in,
                              void* d_out, int out_size)
{
    const int*   seq   = (const int*)  d_in[0];
    const float* Tt    = (const float*)d_in[1];
    const float* Ot    = (const float*)d_in[2];
    const float* pgate = (const float*)d_in[3];
    const float* pop   = (const float*)d_in[4];
    const float* pval  = (const float*)d_in[5];
    const float* initl = (const float*)d_in[6];
    float* out = (float*)d_out;

    cudaFuncSetAttribute(fpt_kernel, cudaFuncAttributeMaxDynamicSharedMemorySize,
                         (int)sizeof(Smem));

    cvt_kernel<<<(unsigned)((TOTAL4 + 255) / 256), 256>>>(Tt, Ot);
    tr_kernel<<<(I_ * S_ * D_ + 255) / 256, 256>>>(pgate, pop, pval);
    fpt_kernel<<<2 * B_, NTHREADS, sizeof(Smem)>>>(seq, initl, out);
}

// round 10
// speedup vs baseline: 1.4052x; 1.1380x over previous
#include <cuda_runtime.h>
#include <cuda_fp16.h>
#include <cstdint>
#include <math.h>

#define S_    64
#define I_    128
#define NO_   64
#define K_    64
#define D_    64
#define B_    64
#define TLEN_ 256
#define THR_  0.01f
#define NTHREADS 1024

#define WELEM  ((size_t)S_ * I_ * D_ * S_)
#define TOTAL4 (WELEM / 4)

__device__ __half g_Th[WELEM];
__device__ __half g_Oh[WELEM];
__device__ float  g_pvt[I_ * S_ * D_];   // pv transposed fp32: [i][s][d]
__device__ __half g_pvh[I_ * S_ * D_];   // pv fp16: [i][d][s]
__device__ float  g_pgt[I_ * S_];        // push_gate transposed: [i][s]
__device__ float  g_ppt[I_ * S_];        // pop_gate transposed:  [i][s]

__global__ __launch_bounds__(256)
void cvt_kernel(const float* __restrict__ Ts, const float* __restrict__ Os) {
    size_t i = (size_t)blockIdx.x * blockDim.x + threadIdx.x;
    if (i >= TOTAL4) return;
    float4 a = ((const float4*)Ts)[i];
    float4 b = ((const float4*)Os)[i];
    __half2 a0 = __floats2half2_rn(a.x, a.y);
    __half2 a1 = __floats2half2_rn(a.z, a.w);
    __half2 b0 = __floats2half2_rn(b.x, b.y);
    __half2 b1 = __floats2half2_rn(b.z, b.w);
    uint2 ua, ub;
    ua.x = *(unsigned*)&a0; ua.y = *(unsigned*)&a1;
    ub.x = *(unsigned*)&b0; ub.y = *(unsigned*)&b1;
    ((uint2*)g_Th)[i] = ua;
    ((uint2*)g_Oh)[i] = ub;
}

__global__ __launch_bounds__(256)
void tr_kernel(const float* __restrict__ pg, const float* __restrict__ pp,
               const float* __restrict__ pv) {
    int idx = blockIdx.x * blockDim.x + threadIdx.x;
    if (idx < I_ * S_ * D_) {
        // g_pvt [i][s][d] (d fastest; coalesced both sides)
        int d = idx & 63;
        int s = (idx >> 6) & 63;
        int i = idx >> 12;
        g_pvt[idx] = pv[(s * I_ + i) * D_ + d];
        // g_pvh [i][d][s] (s fastest; coalesced write, scattered read)
        int s2 = idx & 63;
        int d2 = (idx >> 6) & 63;
        int i2 = idx >> 12;
        g_pvh[idx] = __float2half(pv[(s2 * I_ + i2) * D_ + d2]);
    }
    if (idx < I_ * S_) {
        int s = idx & 63;
        int i = idx >> 6;
        g_pgt[idx] = pg[s * I_ + i];
        g_ppt[idx] = pp[s * I_ + i];
    }
}

// ---------- helpers ----------
__device__ __forceinline__ unsigned int s2u(const void* p) {
    unsigned int a;
    asm("{ .reg .u64 t; cvta.to.shared.u64 t, %1; cvt.u32.u64 %0, t; }" : "=r"(a) : "l"(p));
    return a;
}
__device__ __forceinline__ unsigned int ctarank() {
    unsigned int r; asm("mov.u32 %0, %%cluster_ctarank;" : "=r"(r)); return r;
}
__device__ __forceinline__ float tanh_fast(float x) {
    float y; asm("tanh.approx.f32 %0, %1;" : "=f"(y) : "f"(x)); return y;
}
__device__ __forceinline__ void st_rel_flag(unsigned int a, int v) {
    asm volatile("st.release.cluster.shared::cta.b32 [%0], %1;" :: "r"(a), "r"(v) : "memory");
}
__device__ __forceinline__ int ld_acq_remote(unsigned int laddr, unsigned int peer) {
    unsigned int ra; int v;
    asm("mapa.shared::cluster.u32 %0, %1, %2;" : "=r"(ra) : "r"(laddr), "r"(peer));
    asm volatile("ld.acquire.cluster.shared::cluster.b32 %0, [%1];" : "=r"(v) : "r"(ra) : "memory");
    return v;
}
__device__ __forceinline__ unsigned int ld_remote_u32(unsigned int laddr, unsigned int peer) {
    unsigned int ra, v;
    asm("mapa.shared::cluster.u32 %0, %1, %2;" : "=r"(ra) : "r"(laddr), "r"(peer));
    asm volatile("ld.shared::cluster.b32 %0, [%1];" : "=r"(v) : "r"(ra) : "memory");
    return v;
}

// in-place softmax over 64 values: 8 per lane across an 8-lane group
__device__ __forceinline__ void softmax8(float* a) {
    float m = a[0];
    #pragma unroll
    for (int j = 1; j < 8; j++) m = fmaxf(m, a[j]);
    #pragma unroll
    for (int o = 4; o > 0; o >>= 1) m = fmaxf(m, __shfl_xor_sync(0xffffffffu, m, o, 8));
    float s = 0.f;
    #pragma unroll
    for (int j = 0; j < 8; j++) { a[j] = __expf(a[j] - m); s += a[j]; }
    #pragma unroll
    for (int o = 4; o > 0; o >>= 1) s += __shfl_xor_sync(0xffffffffu, s, o, 8);
    float inv = 1.0f / s;
    #pragma unroll
    for (int j = 0; j < 8; j++) a[j] *= inv;
}

struct __align__(16) Smem {
    float    content[2][K_ * D_];          // 32 KB  (CTA0)
    float    part[32 * 64];                // 8 KB
    float    trace_state[TLEN_ + 1][S_];   // 65.8 KB (CTA0)
    unsigned trace_top[TLEN_ + 1][D_];     // 65.8 KB (CTA0)
    int      flags[TLEN_ + 1];
    int      seq_s[TLEN_ + 1];
    float    pb[2][K_];
    float    pv2[2][D_];
    __half   sh[S_];                       // state(t+1) fp16 for pushv
    float    scal[8];
    float    tstate_l[S_];                 // CTA1 pull buffers
    unsigned ttop_l[D_];
};

// dual-row contraction (fp16 slices, half2 weights tt), post-softmax in fa/fb
__device__ __forceinline__ void contract2(const uint4* __restrict__ A4,
                                          const uint4* __restrict__ B4,
                                          const unsigned int* __restrict__ tt,
                                          int lane, float* fa, float* fb)
{
    const int lr = lane >> 3;
    #pragma unroll
    for (int j = 0; j < 8; j++) { fa[j] = 0.f; fb[j] = 0.f; }
    const __half2 hz = __float2half2_rn(0.f);
    #pragma unroll
    for (int chunk = 0; chunk < 2; chunk++) {
        __half2 hA[4] = {hz, hz, hz, hz};
        __half2 hB[4] = {hz, hz, hz, hz};
        #pragma unroll
        for (int i = 0; i < 8; i++) {
            const int ii = chunk * 8 + i;
            unsigned int tb = tt[ii * 4 + lr];
            const __half2 td2 = *(__half2*)&tb;
            uint4 v = A4[ii * 32 + lane];
            hA[0] = __hfma2(td2, *(__half2*)&v.x, hA[0]);
            hA[1] = __hfma2(td2, *(__half2*)&v.y, hA[1]);
            hA[2] = __hfma2(td2, *(__half2*)&v.z, hA[2]);
            hA[3] = __hfma2(td2, *(__half2*)&v.w, hA[3]);
            uint4 u = B4[ii * 32 + lane];
            hB[0] = __hfma2(td2, *(__half2*)&u.x, hB[0]);
            hB[1] = __hfma2(td2, *(__half2*)&u.y, hB[1]);
            hB[2] = __hfma2(td2, *(__half2*)&u.z, hB[2]);
            hB[3] = __hfma2(td2, *(__half2*)&u.w, hB[3]);
        }
        #pragma unroll
        for (int c = 0; c < 4; c++) {
            float2 f = __half22float2(hA[c]);
            fa[2 * c] += f.x; fa[2 * c + 1] += f.y;
            f = __half22float2(hB[c]);
            fb[2 * c] += f.x; fb[2 * c + 1] += f.y;
        }
    }
    #pragma unroll
    for (int j = 0; j < 8; j++) {
        fa[j] += __shfl_xor_sync(0xffffffffu, fa[j], 8);
        fa[j] += __shfl_xor_sync(0xffffffffu, fa[j], 16);
        fb[j] += __shfl_xor_sync(0xffffffffu, fb[j], 8);
        fb[j] += __shfl_xor_sync(0xffffffffu, fb[j], 16);
    }
    softmax8(fa);
    softmax8(fb);
}

__global__ __launch_bounds__(NTHREADS, 1) __cluster_dims__(2, 1, 1)
void fpt_kernel(const int*   __restrict__ seq,
                const float* __restrict__ initl,
                float*       __restrict__ out)
{
    extern __shared__ char smem_raw[];
    Smem* sm = (Smem*)smem_raw;

    const int tid  = threadIdx.x;
    const int wid  = tid >> 5;
    const int lane = tid & 31;
    const int lc   = lane & 7;
    const int lr   = lane >> 3;
    const unsigned int rank = ctarank();
    const int b    = blockIdx.x >> 1;

    // ---- init (both ranks)
    if (tid < S_) sm->part[tid] = initl[tid];
    for (int e = tid; e <= TLEN_; e += NTHREADS) {
        sm->seq_s[e] = (e < TLEN_) ? seq[b * TLEN_ + e] : 0;
        sm->flags[e] = 0;
    }
    for (int e = tid; e < K_ * D_; e += NTHREADS) sm->content[0][e] = 0.f;
    if (tid < K_) { sm->pb[0][tid] = (tid == 0) ? 1.f : 0.f; sm->pb[1][tid] = 0.f; }
    if (tid < D_) sm->trace_top[0][tid] = 0u;
    __syncthreads();
    if (tid == 0) {
        float m = -1e30f;
        for (int i = 0; i < S_; i++) m = fmaxf(m, sm->part[i]);
        float ssum = 0.f;
        for (int i = 0; i < S_; i++) { float e = expf(sm->part[i] - m); sm->part[64 + i] = e; ssum += e; }
        sm->scal[2] = ssum;
    }
    __syncthreads();
    if (tid < S_) sm->trace_state[0][tid] = sm->part[64 + tid] / sm->scal[2];
    __syncthreads();

    // prologue (rank 0): gates(0), pushv(0) (fp32 path)
    if (rank == 0) {
        const int sym0 = sm->seq_s[0];
        if (wid == 2) {
            float a = g_pgt[sym0 * 64 + lane] * sm->trace_state[0][lane]
                    + g_pgt[sym0 * 64 + 32 + lane] * sm->trace_state[0][lane + 32];
            #pragma unroll
            for (int o = 16; o > 0; o >>= 1) a += __shfl_xor_sync(0xffffffffu, a, o);
            if (lane == 0) sm->scal[0] = 1.f / (1.f + __expf(-a));
        } else if (wid == 3) {
            float a = g_ppt[sym0 * 64 + lane] * sm->trace_state[0][lane]
                    + g_ppt[sym0 * 64 + 32 + lane] * sm->trace_state[0][lane + 32];
            #pragma unroll
            for (int o = 16; o > 0; o >>= 1) a += __shfl_xor_sync(0xffffffffu, a, o);
            if (lane == 0) sm->scal[1] = 1.f / (1.f + __expf(-a));
        } else if (wid >= 6 && wid < 10) {
            const int d  = (wid - 6) * 16 + (lane & 15);
            const int sb = (lane >> 4) * 32;
            float acc = 0.f;
            #pragma unroll 8
            for (int j = 0; j < 32; j++)
                acc += sm->trace_state[0][sb + j] * g_pvt[sym0 * 4096 + (sb + j) * 64 + d];
            acc += __shfl_xor_sync(0xffffffffu, acc, 16);
            if ((lane >> 4) == 0) sm->pv2[0][d] = tanh_fast(acc);
        }
        __syncthreads();
    }

    asm volatile("barrier.cluster.arrive.aligned;" ::: "memory");
    asm volatile("barrier.cluster.wait.aligned;" ::: "memory");

    const unsigned int flags_u = s2u(&sm->flags[0]);

    if (rank == 0) {
        // ===================== recurrence CTA =====================
        const int r0 = wid * 2, r1 = r0 + 1;
        int cb = 0;

        for (int t = 0; t < TLEN_; t++) {
            const int sym  = sm->seq_s[t];
            const int sym1 = sm->seq_s[t + 1];
            const int bp   = t & 1;

            if (tid == 0) st_rel_flag(flags_u + 4u * t, 1);   // publish step t

            // ---- A: pointer update in registers (all warps, redundant)
            const float pushs = sm->scal[0];
            const float pops  = sm->scal[1];
            const int i0 = lane * 2;
            float p0 = sm->pb[bp][i0], p1 = sm->pb[bp][i0 + 1];
            float dd = __shfl_down_sync(0xffffffffu, p0, 1);
            if (lane == 31) dd = 0.f;
            if (pops > THR_) {
                p0 = pops * p1 + (1.f - pops) * p0;
                p1 = pops * dd + (1.f - pops) * p1;
            }
            float uu = __shfl_up_sync(0xffffffffu, p1, 1);
            if (lane == 0) uu = 0.f;
            const float q0 = pushs * uu + (1.f - pushs) * p0;
            const float q1 = pushs * p0 + (1.f - pushs) * p1;
            const bool push = pushs > THR_;
            const float m0 = push ? q0 * (1.f - q0) : p0;
            const float m1 = push ? q1 * (1.f - q1) : p1;
            float cp = push ? (q0 * q0 + q1 * q1) : 0.f;
            #pragma unroll
            for (int o = 16; o > 0; o >>= 1) cp += __shfl_xor_sync(0xffffffffu, cp, o);
            if (wid == 31) {
                sm->pb[bp ^ 1][i0]     = push ? q0 : p0;
                sm->pb[bp ^ 1][i0 + 1] = push ? q1 : p1;
            }

            // ---- B: phase-2 T contraction, combined part row per warp
            {
                float fa[8], fb[8];
                contract2((const uint4*)(g_Th + (size_t)(r0 * I_ + sym) * 4096),
                          (const uint4*)(g_Th + (size_t)(r1 * I_ + sym) * 4096),
                          sm->trace_top[t], lane, fa, fb);
                const float s0 = sm->trace_state[t][r0];
                const float s1 = sm->trace_state[t][r1];
                if (lr == 0) {
                    float4 w;
                    w.x = s0 * fa[0] + s1 * fb[0]; w.y = s0 * fa[1] + s1 * fb[1];
                    w.z = s0 * fa[2] + s1 * fb[2]; w.w = s0 * fa[3] + s1 * fb[3];
                    *(float4*)&sm->part[wid * 64 + lc * 8] = w;
                    w.x = s0 * fa[4] + s1 * fb[4]; w.y = s0 * fa[5] + s1 * fb[5];
                    w.z = s0 * fa[6] + s1 * fb[6]; w.w = s0 * fa[7] + s1 * fb[7];
                    *(float4*)&sm->part[wid * 64 + lc * 8 + 4] = w;
                }
            }
            __syncthreads();   // B1

            // ---- D: reduce || stack_top(t+1) || content update  (parallel)
            if (tid < 64) {
                float ns = 0.f;
                #pragma unroll
                for (int r = 0; r < 32; r++) ns += sm->part[r * 64 + tid];
                sm->trace_state[t + 1][tid] = ns;
                sm->sh[tid] = __float2half(ns);
            } else if (wid >= 2 && wid < 6) {
                const int d  = (wid - 2) * 16 + (lane & 15);
                const int kb = (lane >> 4) * 32;
                float acc = 0.f;
                #pragma unroll 8
                for (int j = 0; j < 32; j++) {
                    float mv = __shfl_sync(0xffffffffu, (j & 1) ? m1 : m0,
                                           (kb >> 1) + (j >> 1));
                    acc += mv * sm->content[cb][(kb + j) * 64 + d];
                }
                acc += __shfl_xor_sync(0xffffffffu, acc, 16);
                if ((lane >> 4) == 0) {
                    __half2 h = __float2half2_rn(acc + cp * sm->pv2[bp][d]);
                    sm->trace_top[t + 1][d] = *(unsigned int*)&h;
                }
            } else if (wid >= 16) {
                if (push) {
                    const int tidc = tid - 512;
                    const int kbase = tidc >> 6;      // warp-uniform
                    const float pvd = sm->pv2[bp][tidc & 63];
                    #pragma unroll
                    for (int i = 0; i < 8; i++) {
                        const int k = kbase + 8 * i;
                        float wk = __shfl_sync(0xffffffffu, (k & 1) ? q1 : q0, k >> 1);
                        const int e = tidc + 512 * i;
                        sm->content[cb ^ 1][e] =
                            sm->content[cb][e] * (1.f - wk) + pvd * wk;
                    }
                }
            }
            __syncthreads();   // B2

            // ---- F: gates(t+1) + pushv(t+1)
            if (wid == 6) {
                float a = g_pgt[sym1 * 64 + lane] * sm->trace_state[t + 1][lane]
                        + g_pgt[sym1 * 64 + 32 + lane] * sm->trace_state[t + 1][lane + 32];
                #pragma unroll
                for (int o = 16; o > 0; o >>= 1) a += __shfl_xor_sync(0xffffffffu, a, o);
                if (lane == 0) sm->scal[0] = 1.f / (1.f + __expf(-a));
            } else if (wid == 7) {
                float a = g_ppt[sym1 * 64 + lane] * sm->trace_state[t + 1][lane]
                        + g_ppt[sym1 * 64 + 32 + lane] * sm->trace_state[t + 1][lane + 32];
                #pragma unroll
                for (int o = 16; o > 0; o >>= 1) a += __shfl_xor_sync(0xffffffffu, a, o);
                if (lane == 0) sm->scal[1] = 1.f / (1.f + __expf(-a));
            } else if (wid >= 8 && wid < 12) {
                const int d   = (wid - 8) * 16 + (lane >> 1);
                const int shh = lane & 1;
                const uint4* pr = (const uint4*)(g_pvh + ((size_t)sym1 * 64 + d) * 64 + shh * 32);
                const __half2* s2 = (const __half2*)sm->sh + shh * 16;
                float a = 0.f;
                #pragma unroll
                for (int u = 0; u < 4; u++) {
                    uint4 v = pr[u];
                    __half2 h0 = __hmul2(s2[u * 4 + 0], *(__half2*)&v.x);
                    __half2 h1 = __hmul2(s2[u * 4 + 1], *(__half2*)&v.y);
                    __half2 h2 = __hmul2(s2[u * 4 + 2], *(__half2*)&v.z);
                    __half2 h3 = __hmul2(s2[u * 4 + 3], *(__half2*)&v.w);
                    float2 f0 = __half22float2(h0), f1 = __half22float2(h1);
                    float2 f2 = __half22float2(h2), f3 = __half22float2(h3);
                    a += (f0.x + f0.y) + (f1.x + f1.y) + (f2.x + f2.y) + (f3.x + f3.y);
                }
                a += __shfl_xor_sync(0xffffffffu, a, 1);
                sm->pv2[bp ^ 1][d] = tanh_fast(a);
            }
            if (push) cb ^= 1;
            __syncthreads();   // B3 / loop top
        }
    } else {
        // ===================== output CTA (lagging consumer) =====================
        const int r0 = wid * 2, r1 = r0 + 1;
        const unsigned int peer = 0u;

        for (int t = 0; t < TLEN_; t++) {
            if (tid == 0) {
                while (ld_acq_remote(flags_u + 4u * t, peer) == 0) { }
            }
            __syncthreads();
            if (tid < 64) {
                unsigned int v = ld_remote_u32(s2u(&sm->trace_state[t][tid]), peer);
                sm->tstate_l[tid] = __uint_as_float(v);
            } else if (tid < 128) {
                sm->ttop_l[tid - 64] = ld_remote_u32(s2u(&sm->trace_top[t][tid - 64]), peer);
            }
            __syncthreads();

            const int sym = sm->seq_s[t];
            float fa[8], fb[8];
            contract2((const uint4*)(g_Oh + (size_t)(r0 * I_ + sym) * 4096),
                      (const uint4*)(g_Oh + (size_t)(r1 * I_ + sym) * 4096),
                      sm->ttop_l, lane, fa, fb);
            const float s0 = sm->tstate_l[r0];
            const float s1 = sm->tstate_l[r1];
            if (lr == 0) {
                float4 w;
                w.x = s0 * fa[0] + s1 * fb[0]; w.y = s0 * fa[1] + s1 * fb[1];
                w.z = s0 * fa[2] + s1 * fb[2]; w.w = s0 * fa[3] + s1 * fb[3];
                *(float4*)&sm->part[wid * 64 + lc * 8] = w;
                w.x = s0 * fa[4] + s1 * fb[4]; w.y = s0 * fa[5] + s1 * fb[5];
                w.z = s0 * fa[6] + s1 * fb[6]; w.w = s0 * fa[7] + s1 * fb[7];
                *(float4*)&sm->part[wid * 64 + lc * 8 + 4] = w;
            }
            __syncthreads();

            if (tid < 64) {
                float m = 0.f;
                #pragma unroll
                for (int r = 0; r < 32; r++) m += sm->part[r * 64 + tid];
                out[((size_t)b * TLEN_ + t) * NO_ + tid] = m;
            }
        }
    }

    asm volatile("barrier.cluster.arrive.aligned;" ::: "memory");
    asm volatile("barrier.cluster.wait.aligned;" ::: "memory");
}

extern "C" void kernel_launch(void* const* d_in, const int* in_sizes, int n_in,
                              void* d_out, int out_size)
{
    const int*   seq   = (const int*)  d_in[0];
    const float* Tt    = (const float*)d_in[1];
    const float* Ot    = (const float*)d_in[2];
    const float* pgate = (const float*)d_in[3];
    const float* pop   = (const float*)d_in[4];
    const float* pval  = (const float*)d_in[5];
    const float* initl = (const float*)d_in[6];
    float* out = (float*)d_out;

    cudaFuncSetAttribute(fpt_kernel, cudaFuncAttributeMaxDynamicSharedMemorySize,
                         (int)sizeof(Smem));

    cvt_kernel<<<(unsigned)((TOTAL4 + 255) / 256), 256>>>(Tt, Ot);
    tr_kernel<<<(I_ * S_ * D_ + 255) / 256, 256>>>(pgate, pop, pval);
    fpt_kernel<<<2 * B_, NTHREADS, sizeof(Smem)>>>(seq, initl, out);
}